// round 3
// baseline (speedup 1.0000x reference)
#include <cuda_runtime.h>
#include <cuda_bf16.h>
#include <cstdint>

#define NN   100000
#define EE   1600000
#define F_IN 128
#define HID  64
#define OUTD 40

// Scratch (device globals — allocation is forbidden)
__device__ float g_uA[NN * HID];
__device__ float g_accA[NN * HID];
__device__ float g_uB[NN * HID];
__device__ float g_accB[NN * HID];
__device__ int   g_deg[NN];
__device__ float g_dis[NN];
__device__ int   g_rowptr[NN];
__device__ int   g_cursor[NN];
__device__ int   g_colidx[EE];
__device__ int   g_bsum[128];

// ---------------------------------------------------------------------------
// scan1: per-1024-chunk exclusive scan of deg -> rowptr, block sums -> bsum.
// Also computes dis = rsqrt(deg+1) (fused; reads deg anyway).
// ---------------------------------------------------------------------------
__global__ void scan1_kernel(const int* __restrict__ deg, int* __restrict__ rowptr,
                             float* __restrict__ dis, int* __restrict__ bsum, int n) {
    __shared__ int sh[256];
    int t = threadIdx.x;
    int base = blockIdx.x * 1024 + t * 4;
    int v[4]; int s = 0;
    #pragma unroll
    for (int j = 0; j < 4; j++) {
        v[j] = (base + j < n) ? deg[base + j] : 0;
        if (base + j < n) dis[base + j] = rsqrtf((float)(v[j] + 1));
        s += v[j];
    }
    sh[t] = s;
    for (int off = 1; off < 256; off <<= 1) {
        __syncthreads();
        int x = (t >= off) ? sh[t - off] : 0;
        __syncthreads();
        sh[t] += x;
    }
    __syncthreads();
    int excl = sh[t] - s;
    int run = 0;
    #pragma unroll
    for (int j = 0; j < 4; j++) {
        if (base + j < n) rowptr[base + j] = excl + run;
        run += v[j];
    }
    if (t == 255) bsum[blockIdx.x] = sh[255];
}

// Parallel exclusive scan of <=128 block sums (one block, 128 threads).
__global__ void scan2_kernel(int* __restrict__ bsum, int nb) {
    __shared__ int sh[128];
    int t = threadIdx.x;
    int v = (t < nb) ? bsum[t] : 0;
    sh[t] = v;
    for (int off = 1; off < 128; off <<= 1) {
        __syncthreads();
        int x = (t >= off) ? sh[t - off] : 0;
        __syncthreads();
        sh[t] += x;
    }
    __syncthreads();
    if (t < nb) bsum[t] = sh[t] - v;
}

__global__ void scan3_kernel(const int* __restrict__ bsum, int* __restrict__ rowptr,
                             int* __restrict__ cursor, int n) {
    int i = blockIdx.x * blockDim.x + threadIdx.x;
    if (i < n) {
        int r = rowptr[i] + bsum[i >> 10];
        rowptr[i] = r;
        cursor[i] = r;
    }
}

__global__ void scatter_kernel(const int* __restrict__ src, const int* __restrict__ dst,
                               int* __restrict__ cursor, int* __restrict__ colidx, int E) {
    int e = blockIdx.x * blockDim.x + threadIdx.x;
    if (e < E) {
        int p = atomicAdd(&cursor[dst[e]], 1);
        colidx[p] = src[e];
    }
}

// ---------------------------------------------------------------------------
// GEMM NOUT=64 with packed fma.rn.f32x2. Block 256 thr -> 32 rows x 64 cols.
// Heterogeneous grid: blocks >= gemmBlocks do the degree histogram instead
// (grid-stride over edges) so count_deg overlaps the layer-0 GEMM.
// ---------------------------------------------------------------------------
template<int K, bool RELU_IN, bool SCALE_OUT>
__global__ void gemm64_kernel(const float* __restrict__ X,
                              const float* __restrict__ W,
                              const float* __restrict__ B,
                              const float* __restrict__ dis,
                              float* __restrict__ u, int n,
                              const int* __restrict__ edge_dst, int E,
                              int* __restrict__ deg, int gemmBlocks) {
    constexpr int KC = 64;
    constexpr int XSTR = KC + 1;
    __shared__ float  Ws[KC * 64];
    __shared__ float2 Xd[32 * XSTR];

    int t = threadIdx.x;

    if ((int)blockIdx.x >= gemmBlocks) {
        // degree-count blocks
        int nb = gridDim.x - gemmBlocks;
        int stride = nb * 256;
        for (int e = (blockIdx.x - gemmBlocks) * 256 + t; e < E; e += stride)
            atomicAdd(&deg[__ldg(edge_dst + e)], 1);
        return;
    }

    int row0 = blockIdx.x * 32;
    int tix = t & 15;
    int tiy = t >> 4;

    unsigned long long acc[2][2];
    acc[0][0] = acc[0][1] = acc[1][0] = acc[1][1] = 0ull;

    for (int k0 = 0; k0 < K; k0 += KC) {
        #pragma unroll
        for (int i = t; i < KC * 64 / 4; i += 256)
            ((float4*)Ws)[i] = ((const float4*)(W + k0 * 64))[i];
        #pragma unroll
        for (int i = t; i < 32 * KC / 4; i += 256) {
            int r = i / (KC / 4);
            int c = (i % (KC / 4)) * 4;
            int gr = row0 + r;
            float4 x = {0.f, 0.f, 0.f, 0.f};
            if (gr < n) {
                x = *(const float4*)(X + (size_t)gr * K + k0 + c);
                if (RELU_IN) {
                    float s = dis[gr];
                    x.x = fmaxf(x.x, 0.f) * s; x.y = fmaxf(x.y, 0.f) * s;
                    x.z = fmaxf(x.z, 0.f) * s; x.w = fmaxf(x.w, 0.f) * s;
                }
            }
            float2* p = &Xd[r * XSTR + c];
            p[0] = make_float2(x.x, x.x); p[1] = make_float2(x.y, x.y);
            p[2] = make_float2(x.z, x.z); p[3] = make_float2(x.w, x.w);
        }
        __syncthreads();

        #pragma unroll
        for (int k = 0; k < KC; k++) {
            ulonglong2 w = *reinterpret_cast<const ulonglong2*>(&Ws[k * 64 + tix * 4]);
            unsigned long long x0 = *reinterpret_cast<const unsigned long long*>(&Xd[(tiy * 2 + 0) * XSTR + k]);
            unsigned long long x1 = *reinterpret_cast<const unsigned long long*>(&Xd[(tiy * 2 + 1) * XSTR + k]);
            asm("fma.rn.f32x2 %0, %1, %2, %0;" : "+l"(acc[0][0]) : "l"(x0), "l"(w.x));
            asm("fma.rn.f32x2 %0, %1, %2, %0;" : "+l"(acc[0][1]) : "l"(x0), "l"(w.y));
            asm("fma.rn.f32x2 %0, %1, %2, %0;" : "+l"(acc[1][0]) : "l"(x1), "l"(w.x));
            asm("fma.rn.f32x2 %0, %1, %2, %0;" : "+l"(acc[1][1]) : "l"(x1), "l"(w.y));
        }
        __syncthreads();
    }

    float4 b4 = *(const float4*)(B + tix * 4);
    #pragma unroll
    for (int r = 0; r < 2; r++) {
        int gr = row0 + tiy * 2 + r;
        if (gr >= n) continue;
        float s = SCALE_OUT ? dis[gr] : 1.f;
        float4 o;
        o.x = (__uint_as_float((unsigned)(acc[r][0] & 0xffffffffu)) + b4.x) * s;
        o.y = (__uint_as_float((unsigned)(acc[r][0] >> 32))         + b4.y) * s;
        o.z = (__uint_as_float((unsigned)(acc[r][1] & 0xffffffffu)) + b4.z) * s;
        o.w = (__uint_as_float((unsigned)(acc[r][1] >> 32))         + b4.w) * s;
        *(float4*)(u + (size_t)gr * 64 + tix * 4) = o;
    }
}

// ---------------------------------------------------------------------------
// Output head GEMM (NOUT=40)
// ---------------------------------------------------------------------------
template<int K, int NOUT>
__global__ void gemm_head_kernel(const float* __restrict__ X,
                                 const float* __restrict__ W,
                                 const float* __restrict__ B,
                                 const float* __restrict__ dis,
                                 float* __restrict__ out, int n) {
    __shared__ float Ws[K * NOUT];
    __shared__ float Xs[32 * K];

    int t = threadIdx.x;
    int row0 = blockIdx.x * 32;

    #pragma unroll 4
    for (int i = t; i < K * NOUT; i += 256) Ws[i] = W[i];
    #pragma unroll 4
    for (int i = t; i < 32 * K; i += 256) {
        int r = i / K, k = i - r * K;
        int gr = row0 + r;
        float v = 0.f;
        if (gr < n) v = fmaxf(X[(size_t)gr * K + k], 0.f) * dis[gr];
        Xs[i] = v;
    }
    __syncthreads();

    int warp = t >> 5, lane = t & 31;
    int r0 = warp * 4;
    float acc0[4] = {0.f, 0.f, 0.f, 0.f};
    float acc1[4] = {0.f, 0.f, 0.f, 0.f};

    #pragma unroll
    for (int k = 0; k < K; k++) {
        float w0 = Ws[k * NOUT + lane];
        float w1 = (lane + 32 < NOUT) ? Ws[k * NOUT + lane + 32] : 0.f;
        #pragma unroll
        for (int r = 0; r < 4; r++) {
            float xv = Xs[(r0 + r) * K + k];
            acc0[r] = fmaf(xv, w0, acc0[r]);
            acc1[r] = fmaf(xv, w1, acc1[r]);
        }
    }

    float b0 = B[lane];
    float b1 = (lane + 32 < NOUT) ? B[lane + 32] : 0.f;
    #pragma unroll
    for (int r = 0; r < 4; r++) {
        int gr = row0 + r0 + r;
        if (gr >= n) continue;
        out[(size_t)gr * NOUT + lane] = acc0[r] + b0;
        if (lane + 32 < NOUT) out[(size_t)gr * NOUT + lane + 32] = acc1[r] + b1;
    }
}

// ---------------------------------------------------------------------------
// Pull aggregation, unroll 4 with dual accumulators (MLP=4).
// WEIGHTED=true (layer 0): acc[v] = dis[v]*u[v] + sum dis[s]*u[s]
// WEIGHTED=false:          acc[v] = u[v] + sum u[s]
// Half-warp (16 lanes) per node, float4 per lane.
// ---------------------------------------------------------------------------
template<bool WEIGHTED>
__global__ void pull_kernel(const int* __restrict__ rowptr,
                            const int* __restrict__ deg,
                            const int* __restrict__ colidx,
                            const float* __restrict__ dis,
                            const float* __restrict__ u,
                            float* __restrict__ acc, int n) {
    int idx = blockIdx.x * blockDim.x + threadIdx.x;
    int v = idx >> 4;
    if (v >= n) return;
    int h = idx & 15;

    const float4* uv = (const float4*)u;
    float4 a0 = __ldg(uv + (size_t)v * 16 + h);
    if (WEIGHTED) {
        float sv = __ldg(dis + v);
        a0.x *= sv; a0.y *= sv; a0.z *= sv; a0.w *= sv;
    }
    float4 a1 = {0.f, 0.f, 0.f, 0.f};
    int s0 = __ldg(rowptr + v);
    int d  = __ldg(deg + v);

    int j = 0;
    for (; j + 4 <= d; j += 4) {
        int c0 = __ldg(colidx + s0 + j);
        int c1 = __ldg(colidx + s0 + j + 1);
        int c2 = __ldg(colidx + s0 + j + 2);
        int c3 = __ldg(colidx + s0 + j + 3);
        float4 x0 = __ldg(uv + (size_t)c0 * 16 + h);
        float4 x1 = __ldg(uv + (size_t)c1 * 16 + h);
        float4 x2 = __ldg(uv + (size_t)c2 * 16 + h);
        float4 x3 = __ldg(uv + (size_t)c3 * 16 + h);
        if (WEIGHTED) {
            float w0 = __ldg(dis + c0), w1 = __ldg(dis + c1);
            float w2 = __ldg(dis + c2), w3 = __ldg(dis + c3);
            a0.x = fmaf(w0, x0.x, a0.x); a0.y = fmaf(w0, x0.y, a0.y);
            a0.z = fmaf(w0, x0.z, a0.z); a0.w = fmaf(w0, x0.w, a0.w);
            a1.x = fmaf(w1, x1.x, a1.x); a1.y = fmaf(w1, x1.y, a1.y);
            a1.z = fmaf(w1, x1.z, a1.z); a1.w = fmaf(w1, x1.w, a1.w);
            a0.x = fmaf(w2, x2.x, a0.x); a0.y = fmaf(w2, x2.y, a0.y);
            a0.z = fmaf(w2, x2.z, a0.z); a0.w = fmaf(w2, x2.w, a0.w);
            a1.x = fmaf(w3, x3.x, a1.x); a1.y = fmaf(w3, x3.y, a1.y);
            a1.z = fmaf(w3, x3.z, a1.z); a1.w = fmaf(w3, x3.w, a1.w);
        } else {
            a0.x += x0.x; a0.y += x0.y; a0.z += x0.z; a0.w += x0.w;
            a1.x += x1.x; a1.y += x1.y; a1.z += x1.z; a1.w += x1.w;
            a0.x += x2.x; a0.y += x2.y; a0.z += x2.z; a0.w += x2.w;
            a1.x += x3.x; a1.y += x3.y; a1.z += x3.z; a1.w += x3.w;
        }
    }
    for (; j < d; j++) {
        int c0 = __ldg(colidx + s0 + j);
        float4 x0 = __ldg(uv + (size_t)c0 * 16 + h);
        if (WEIGHTED) {
            float w0 = __ldg(dis + c0);
            a0.x = fmaf(w0, x0.x, a0.x); a0.y = fmaf(w0, x0.y, a0.y);
            a0.z = fmaf(w0, x0.z, a0.z); a0.w = fmaf(w0, x0.w, a0.w);
        } else {
            a0.x += x0.x; a0.y += x0.y; a0.z += x0.z; a0.w += x0.w;
        }
    }
    a0.x += a1.x; a0.y += a1.y; a0.z += a1.z; a0.w += a1.w;
    ((float4*)acc)[(size_t)v * 16 + h] = a0;
}

// ---------------------------------------------------------------------------
extern "C" void kernel_launch(void* const* d_in, const int* in_sizes, int n_in,
                              void* d_out, int out_size) {
    const float* x    = (const float*)d_in[0];
    const int*   ei   = (const int*)d_in[1];
    const float* W0   = (const float*)d_in[2];
    const float* b0   = (const float*)d_in[3];
    const float* W1   = (const float*)d_in[4];
    const float* b1   = (const float*)d_in[5];
    const float* W2   = (const float*)d_in[6];
    const float* b2   = (const float*)d_in[7];
    const float* Wout = (const float*)d_in[8];
    const float* bout = (const float*)d_in[9];
    float* out = (float*)d_out;

    const int N = in_sizes[0] / F_IN;
    const int E = in_sizes[1] / 2;
    const int* src = ei;
    const int* dst = ei + E;

    float *uA, *accA, *uB, *accB, *dis;
    int *deg, *rowptr, *cursor, *colidx, *bsum;
    cudaGetSymbolAddress((void**)&uA,     g_uA);
    cudaGetSymbolAddress((void**)&accA,   g_accA);
    cudaGetSymbolAddress((void**)&uB,     g_uB);
    cudaGetSymbolAddress((void**)&accB,   g_accB);
    cudaGetSymbolAddress((void**)&deg,    g_deg);
    cudaGetSymbolAddress((void**)&dis,    g_dis);
    cudaGetSymbolAddress((void**)&rowptr, g_rowptr);
    cudaGetSymbolAddress((void**)&cursor, g_cursor);
    cudaGetSymbolAddress((void**)&colidx, g_colidx);
    cudaGetSymbolAddress((void**)&bsum,   g_bsum);

    const int TPB = 256;
    int gemmBlocks = (N + 31) / 32;              // 3125
    int countBlocks = 2048;
    dim3 fused_grid(gemmBlocks + countBlocks);
    dim3 g64_grid(gemmBlocks);
    dim3 pull_grid(((size_t)N * 16 + TPB - 1) / TPB);
    int nscan = (N + 1023) / 1024;               // 98 <= 128

    // Layer-0 GEMM (unscaled -> no dis dependency) fused with degree count
    cudaMemsetAsync(deg, 0, N * sizeof(int), 0);
    gemm64_kernel<F_IN, false, false><<<fused_grid, TPB>>>(
        x, W0, b0, dis, uA, N, dst, E, deg, gemmBlocks);

    // CSR build (dst-grouped) + dis
    scan1_kernel<<<nscan, 256>>>(deg, rowptr, dis, bsum, N);
    scan2_kernel<<<1, 128>>>(bsum, nscan);
    scan3_kernel<<<(N + TPB - 1) / TPB, TPB>>>(bsum, rowptr, cursor, N);
    scatter_kernel<<<(E + TPB - 1) / TPB, TPB>>>(src, dst, cursor, colidx, E);

    // Layer 0 aggregation (weighted: applies dis[src] and dis-self here)
    pull_kernel<true><<<pull_grid, TPB>>>(rowptr, deg, colidx, dis, uA, accA, N);
    // Layer 1
    gemm64_kernel<HID, true, true><<<g64_grid, TPB>>>(accA, W1, b1, dis, uB, N, nullptr, 0, nullptr, gemmBlocks);
    pull_kernel<false><<<pull_grid, TPB>>>(rowptr, deg, colidx, dis, uB, accB, N);
    // Layer 2
    gemm64_kernel<HID, true, true><<<g64_grid, TPB>>>(accB, W2, b2, dis, uA, N, nullptr, 0, nullptr, gemmBlocks);
    pull_kernel<false><<<pull_grid, TPB>>>(rowptr, deg, colidx, dis, uA, accA, N);
    // Head
    gemm_head_kernel<HID, OUTD><<<g64_grid, TPB>>>(accA, Wout, bout, dis, out, N);
}

// round 4
// speedup vs baseline: 1.0418x; 1.0418x over previous
#include <cuda_runtime.h>
#include <cuda_fp16.h>
#include <cstdint>

#define NN   100000
#define EE   1600000
#define F_IN 128
#define HID  64
#define OUTD 40

// Scratch (device globals — allocation is forbidden)
__device__ __half g_uA[NN * HID];     // fp16 messages
__device__ __half g_uB[NN * HID];
__device__ float  g_accA[NN * HID];   // fp32 aggregation results
__device__ float  g_accB[NN * HID];
__device__ int    g_deg[NN];
__device__ float  g_dis[NN];
__device__ int    g_rowptr[NN];
__device__ int    g_cursor[NN];
__device__ int    g_colidx[EE];
__device__ int    g_bsum[128];

// ---------------------------------------------------------------------------
// scan1: per-1024-chunk exclusive scan of deg -> rowptr + dis = rsqrt(deg+1)
// ---------------------------------------------------------------------------
__global__ void scan1_kernel(const int* __restrict__ deg, int* __restrict__ rowptr,
                             float* __restrict__ dis, int* __restrict__ bsum, int n) {
    __shared__ int sh[256];
    int t = threadIdx.x;
    int base = blockIdx.x * 1024 + t * 4;
    int v[4]; int s = 0;
    #pragma unroll
    for (int j = 0; j < 4; j++) {
        v[j] = (base + j < n) ? deg[base + j] : 0;
        if (base + j < n) dis[base + j] = rsqrtf((float)(v[j] + 1));
        s += v[j];
    }
    sh[t] = s;
    for (int off = 1; off < 256; off <<= 1) {
        __syncthreads();
        int x = (t >= off) ? sh[t - off] : 0;
        __syncthreads();
        sh[t] += x;
    }
    __syncthreads();
    int excl = sh[t] - s;
    int run = 0;
    #pragma unroll
    for (int j = 0; j < 4; j++) {
        if (base + j < n) rowptr[base + j] = excl + run;
        run += v[j];
    }
    if (t == 255) bsum[blockIdx.x] = sh[255];
}

__global__ void scan2_kernel(int* __restrict__ bsum, int nb) {
    __shared__ int sh[128];
    int t = threadIdx.x;
    int v = (t < nb) ? bsum[t] : 0;
    sh[t] = v;
    for (int off = 1; off < 128; off <<= 1) {
        __syncthreads();
        int x = (t >= off) ? sh[t - off] : 0;
        __syncthreads();
        sh[t] += x;
    }
    __syncthreads();
    if (t < nb) bsum[t] = sh[t] - v;
}

__global__ void scan3_kernel(const int* __restrict__ bsum, int* __restrict__ rowptr,
                             int* __restrict__ cursor, int n) {
    int i = blockIdx.x * blockDim.x + threadIdx.x;
    if (i < n) {
        int r = rowptr[i] + bsum[i >> 10];
        rowptr[i] = r;
        cursor[i] = r;
    }
}

__global__ void scatter_kernel(const int* __restrict__ src, const int* __restrict__ dst,
                               int* __restrict__ cursor, int* __restrict__ colidx, int E) {
    int e = blockIdx.x * blockDim.x + threadIdx.x;
    if (e < E) {
        int p = atomicAdd(&cursor[dst[e]], 1);
        colidx[p] = src[e];
    }
}

// ---------------------------------------------------------------------------
// GEMM NOUT=64, packed fma.rn.f32x2, fp16 output u.
// Heterogeneous grid: trailing blocks do the degree histogram (layer 0 only).
// ---------------------------------------------------------------------------
template<int K, bool RELU_IN, bool SCALE_OUT>
__global__ void gemm64_kernel(const float* __restrict__ X,
                              const float* __restrict__ W,
                              const float* __restrict__ B,
                              const float* __restrict__ dis,
                              __half* __restrict__ u, int n,
                              const int* __restrict__ edge_dst, int E,
                              int* __restrict__ deg, int gemmBlocks) {
    constexpr int KC = 64;
    constexpr int XSTR = KC + 1;
    __shared__ float  Ws[KC * 64];
    __shared__ float2 Xd[32 * XSTR];

    int t = threadIdx.x;

    if ((int)blockIdx.x >= gemmBlocks) {
        int nb = gridDim.x - gemmBlocks;
        int stride = nb * 256;
        for (int e = (blockIdx.x - gemmBlocks) * 256 + t; e < E; e += stride)
            atomicAdd(&deg[__ldg(edge_dst + e)], 1);
        return;
    }

    int row0 = blockIdx.x * 32;
    int tix = t & 15;
    int tiy = t >> 4;

    unsigned long long acc[2][2];
    acc[0][0] = acc[0][1] = acc[1][0] = acc[1][1] = 0ull;

    for (int k0 = 0; k0 < K; k0 += KC) {
        #pragma unroll
        for (int i = t; i < KC * 64 / 4; i += 256)
            ((float4*)Ws)[i] = ((const float4*)(W + k0 * 64))[i];
        #pragma unroll
        for (int i = t; i < 32 * KC / 4; i += 256) {
            int r = i / (KC / 4);
            int c = (i % (KC / 4)) * 4;
            int gr = row0 + r;
            float4 x = {0.f, 0.f, 0.f, 0.f};
            if (gr < n) {
                x = *(const float4*)(X + (size_t)gr * K + k0 + c);
                if (RELU_IN) {
                    float s = dis[gr];
                    x.x = fmaxf(x.x, 0.f) * s; x.y = fmaxf(x.y, 0.f) * s;
                    x.z = fmaxf(x.z, 0.f) * s; x.w = fmaxf(x.w, 0.f) * s;
                }
            }
            float2* p = &Xd[r * XSTR + c];
            p[0] = make_float2(x.x, x.x); p[1] = make_float2(x.y, x.y);
            p[2] = make_float2(x.z, x.z); p[3] = make_float2(x.w, x.w);
        }
        __syncthreads();

        #pragma unroll
        for (int k = 0; k < KC; k++) {
            ulonglong2 w = *reinterpret_cast<const ulonglong2*>(&Ws[k * 64 + tix * 4]);
            unsigned long long x0 = *reinterpret_cast<const unsigned long long*>(&Xd[(tiy * 2 + 0) * XSTR + k]);
            unsigned long long x1 = *reinterpret_cast<const unsigned long long*>(&Xd[(tiy * 2 + 1) * XSTR + k]);
            asm("fma.rn.f32x2 %0, %1, %2, %0;" : "+l"(acc[0][0]) : "l"(x0), "l"(w.x));
            asm("fma.rn.f32x2 %0, %1, %2, %0;" : "+l"(acc[0][1]) : "l"(x0), "l"(w.y));
            asm("fma.rn.f32x2 %0, %1, %2, %0;" : "+l"(acc[1][0]) : "l"(x1), "l"(w.x));
            asm("fma.rn.f32x2 %0, %1, %2, %0;" : "+l"(acc[1][1]) : "l"(x1), "l"(w.y));
        }
        __syncthreads();
    }

    float4 b4 = *(const float4*)(B + tix * 4);
    #pragma unroll
    for (int r = 0; r < 2; r++) {
        int gr = row0 + tiy * 2 + r;
        if (gr >= n) continue;
        float s = SCALE_OUT ? dis[gr] : 1.f;
        float o0 = (__uint_as_float((unsigned)(acc[r][0] & 0xffffffffu)) + b4.x) * s;
        float o1 = (__uint_as_float((unsigned)(acc[r][0] >> 32))         + b4.y) * s;
        float o2 = (__uint_as_float((unsigned)(acc[r][1] & 0xffffffffu)) + b4.z) * s;
        float o3 = (__uint_as_float((unsigned)(acc[r][1] >> 32))         + b4.w) * s;
        __half2 h01 = __floats2half2_rn(o0, o1);
        __half2 h23 = __floats2half2_rn(o2, o3);
        uint2 pk = make_uint2(*(unsigned*)&h01, *(unsigned*)&h23);
        *(uint2*)(u + (size_t)gr * 64 + tix * 4) = pk;
    }
}

// ---------------------------------------------------------------------------
// Output head GEMM (NOUT=40), fp32 in/out
// ---------------------------------------------------------------------------
template<int K, int NOUT>
__global__ void gemm_head_kernel(const float* __restrict__ X,
                                 const float* __restrict__ W,
                                 const float* __restrict__ B,
                                 const float* __restrict__ dis,
                                 float* __restrict__ out, int n) {
    __shared__ float Ws[K * NOUT];
    __shared__ float Xs[32 * K];

    int t = threadIdx.x;
    int row0 = blockIdx.x * 32;

    #pragma unroll 4
    for (int i = t; i < K * NOUT; i += 256) Ws[i] = W[i];
    #pragma unroll 4
    for (int i = t; i < 32 * K; i += 256) {
        int r = i / K, k = i - r * K;
        int gr = row0 + r;
        float v = 0.f;
        if (gr < n) v = fmaxf(X[(size_t)gr * K + k], 0.f) * dis[gr];
        Xs[i] = v;
    }
    __syncthreads();

    int warp = t >> 5, lane = t & 31;
    int r0 = warp * 4;
    float acc0[4] = {0.f, 0.f, 0.f, 0.f};
    float acc1[4] = {0.f, 0.f, 0.f, 0.f};

    #pragma unroll
    for (int k = 0; k < K; k++) {
        float w0 = Ws[k * NOUT + lane];
        float w1 = (lane + 32 < NOUT) ? Ws[k * NOUT + lane + 32] : 0.f;
        #pragma unroll
        for (int r = 0; r < 4; r++) {
            float xv = Xs[(r0 + r) * K + k];
            acc0[r] = fmaf(xv, w0, acc0[r]);
            acc1[r] = fmaf(xv, w1, acc1[r]);
        }
    }

    float b0 = B[lane];
    float b1 = (lane + 32 < NOUT) ? B[lane + 32] : 0.f;
    #pragma unroll
    for (int r = 0; r < 4; r++) {
        int gr = row0 + r0 + r;
        if (gr >= n) continue;
        out[(size_t)gr * NOUT + lane] = acc0[r] + b0;
        if (lane + 32 < NOUT) out[(size_t)gr * NOUT + lane + 32] = acc1[r] + b1;
    }
}

// ---------------------------------------------------------------------------
// Pull aggregation over fp16 messages, fp32 accumulation.
// Half-warp (16 lanes) per node; lane h covers halfs [h*4, h*4+4) = uint2.
// WEIGHTED=true (layer 0): acc[v] = dis[v]*u[v] + sum dis[s]*u[s]
// ---------------------------------------------------------------------------
template<bool WEIGHTED>
__global__ void pull_kernel(const int* __restrict__ rowptr,
                            const int* __restrict__ deg,
                            const int* __restrict__ colidx,
                            const float* __restrict__ dis,
                            const __half* __restrict__ u,
                            float* __restrict__ acc, int n) {
    int idx = blockIdx.x * blockDim.x + threadIdx.x;
    int v = idx >> 4;
    if (v >= n) return;
    int h = idx & 15;

    const uint2* uv = (const uint2*)u;   // row stride = 16 uint2

    float4 a0, a1 = {0.f, 0.f, 0.f, 0.f};
    {
        uint2 pk = __ldg(uv + (size_t)v * 16 + h);
        float2 f01 = __half22float2(*(const __half2*)&pk.x);
        float2 f23 = __half22float2(*(const __half2*)&pk.y);
        float sv = WEIGHTED ? __ldg(dis + v) : 1.f;
        a0.x = f01.x * sv; a0.y = f01.y * sv; a0.z = f23.x * sv; a0.w = f23.y * sv;
    }
    int s0 = __ldg(rowptr + v);
    int d  = __ldg(deg + v);

    int j = 0;
    for (; j + 4 <= d; j += 4) {
        int c0 = __ldg(colidx + s0 + j);
        int c1 = __ldg(colidx + s0 + j + 1);
        int c2 = __ldg(colidx + s0 + j + 2);
        int c3 = __ldg(colidx + s0 + j + 3);
        uint2 p0 = __ldg(uv + (size_t)c0 * 16 + h);
        uint2 p1 = __ldg(uv + (size_t)c1 * 16 + h);
        uint2 p2 = __ldg(uv + (size_t)c2 * 16 + h);
        uint2 p3 = __ldg(uv + (size_t)c3 * 16 + h);
        float2 f0a = __half22float2(*(const __half2*)&p0.x), f0b = __half22float2(*(const __half2*)&p0.y);
        float2 f1a = __half22float2(*(const __half2*)&p1.x), f1b = __half22float2(*(const __half2*)&p1.y);
        float2 f2a = __half22float2(*(const __half2*)&p2.x), f2b = __half22float2(*(const __half2*)&p2.y);
        float2 f3a = __half22float2(*(const __half2*)&p3.x), f3b = __half22float2(*(const __half2*)&p3.y);
        if (WEIGHTED) {
            float w0 = __ldg(dis + c0), w1 = __ldg(dis + c1);
            float w2 = __ldg(dis + c2), w3 = __ldg(dis + c3);
            a0.x = fmaf(w0, f0a.x, a0.x); a0.y = fmaf(w0, f0a.y, a0.y);
            a0.z = fmaf(w0, f0b.x, a0.z); a0.w = fmaf(w0, f0b.y, a0.w);
            a1.x = fmaf(w1, f1a.x, a1.x); a1.y = fmaf(w1, f1a.y, a1.y);
            a1.z = fmaf(w1, f1b.x, a1.z); a1.w = fmaf(w1, f1b.y, a1.w);
            a0.x = fmaf(w2, f2a.x, a0.x); a0.y = fmaf(w2, f2a.y, a0.y);
            a0.z = fmaf(w2, f2b.x, a0.z); a0.w = fmaf(w2, f2b.y, a0.w);
            a1.x = fmaf(w3, f3a.x, a1.x); a1.y = fmaf(w3, f3a.y, a1.y);
            a1.z = fmaf(w3, f3b.x, a1.z); a1.w = fmaf(w3, f3b.y, a1.w);
        } else {
            a0.x += f0a.x; a0.y += f0a.y; a0.z += f0b.x; a0.w += f0b.y;
            a1.x += f1a.x; a1.y += f1a.y; a1.z += f1b.x; a1.w += f1b.y;
            a0.x += f2a.x; a0.y += f2a.y; a0.z += f2b.x; a0.w += f2b.y;
            a1.x += f3a.x; a1.y += f3a.y; a1.z += f3b.x; a1.w += f3b.y;
        }
    }
    for (; j < d; j++) {
        int c0 = __ldg(colidx + s0 + j);
        uint2 p0 = __ldg(uv + (size_t)c0 * 16 + h);
        float2 f0a = __half22float2(*(const __half2*)&p0.x), f0b = __half22float2(*(const __half2*)&p0.y);
        float w0 = WEIGHTED ? __ldg(dis + c0) : 1.f;
        a0.x = fmaf(w0, f0a.x, a0.x); a0.y = fmaf(w0, f0a.y, a0.y);
        a0.z = fmaf(w0, f0b.x, a0.z); a0.w = fmaf(w0, f0b.y, a0.w);
    }
    a0.x += a1.x; a0.y += a1.y; a0.z += a1.z; a0.w += a1.w;
    *(float4*)(acc + (size_t)v * 64 + h * 4) = a0;
}

// ---------------------------------------------------------------------------
extern "C" void kernel_launch(void* const* d_in, const int* in_sizes, int n_in,
                              void* d_out, int out_size) {
    const float* x    = (const float*)d_in[0];
    const int*   ei   = (const int*)d_in[1];
    const float* W0   = (const float*)d_in[2];
    const float* b0   = (const float*)d_in[3];
    const float* W1   = (const float*)d_in[4];
    const float* b1   = (const float*)d_in[5];
    const float* W2   = (const float*)d_in[6];
    const float* b2   = (const float*)d_in[7];
    const float* Wout = (const float*)d_in[8];
    const float* bout = (const float*)d_in[9];
    float* out = (float*)d_out;

    const int N = in_sizes[0] / F_IN;
    const int E = in_sizes[1] / 2;
    const int* src = ei;
    const int* dst = ei + E;

    __half *uA, *uB;
    float *accA, *accB, *dis;
    int *deg, *rowptr, *cursor, *colidx, *bsum;
    cudaGetSymbolAddress((void**)&uA,     g_uA);
    cudaGetSymbolAddress((void**)&uB,     g_uB);
    cudaGetSymbolAddress((void**)&accA,   g_accA);
    cudaGetSymbolAddress((void**)&accB,   g_accB);
    cudaGetSymbolAddress((void**)&deg,    g_deg);
    cudaGetSymbolAddress((void**)&dis,    g_dis);
    cudaGetSymbolAddress((void**)&rowptr, g_rowptr);
    cudaGetSymbolAddress((void**)&cursor, g_cursor);
    cudaGetSymbolAddress((void**)&colidx, g_colidx);
    cudaGetSymbolAddress((void**)&bsum,   g_bsum);

    const int TPB = 256;
    int gemmBlocks = (N + 31) / 32;
    int countBlocks = 2048;
    dim3 fused_grid(gemmBlocks + countBlocks);
    dim3 g64_grid(gemmBlocks);
    dim3 pull_grid(((size_t)N * 16 + TPB - 1) / TPB);
    int nscan = (N + 1023) / 1024;

    // Layer-0 GEMM (no dis dependency; unscaled output) fused with degree count
    cudaMemsetAsync(deg, 0, N * sizeof(int), 0);
    gemm64_kernel<F_IN, false, false><<<fused_grid, TPB>>>(
        x, W0, b0, dis, uA, N, dst, E, deg, gemmBlocks);

    // CSR build (dst-grouped) + dis
    scan1_kernel<<<nscan, 256>>>(deg, rowptr, dis, bsum, N);
    scan2_kernel<<<1, 128>>>(bsum, nscan);
    scan3_kernel<<<(N + TPB - 1) / TPB, TPB>>>(bsum, rowptr, cursor, N);
    scatter_kernel<<<(E + TPB - 1) / TPB, TPB>>>(src, dst, cursor, colidx, E);

    // Layer 0 aggregation (weighted: applies dis[src] and dis[v] here)
    pull_kernel<true><<<pull_grid, TPB>>>(rowptr, deg, colidx, dis, uA, accA, N);
    // Layer 1
    gemm64_kernel<HID, true, true><<<g64_grid, TPB>>>(accA, W1, b1, dis, uB, N, nullptr, 0, nullptr, gemmBlocks);
    pull_kernel<false><<<pull_grid, TPB>>>(rowptr, deg, colidx, dis, uB, accB, N);
    // Layer 2
    gemm64_kernel<HID, true, true><<<g64_grid, TPB>>>(accB, W2, b2, dis, uA, N, nullptr, 0, nullptr, gemmBlocks);
    pull_kernel<false><<<pull_grid, TPB>>>(rowptr, deg, colidx, dis, uA, accA, N);
    // Head
    gemm_head_kernel<HID, OUTD><<<g64_grid, TPB>>>(accA, Wout, bout, dis, out, N);
}

// round 5
// speedup vs baseline: 1.1359x; 1.0904x over previous
#include <cuda_runtime.h>
#include <cuda_fp16.h>
#include <cstdint>

#define NN   100000
#define EE   1600000
#define F_IN 128
#define HID  64
#define OUTD 40

// Scratch (device globals — allocation is forbidden)
__device__ __half g_uA[NN * HID];     // fp16 messages
__device__ __half g_uB[NN * HID];
__device__ float  g_accA[NN * HID];   // fp32 aggregation results
__device__ float  g_accB[NN * HID];
__device__ int    g_deg[NN];
__device__ float  g_dis[NN];
__device__ __half g_dish[NN];         // fp16 copy of dis for HFMA2 path
__device__ int    g_rowptr[NN];
__device__ int    g_cursor[NN];
__device__ int    g_colidx[EE];
__device__ int    g_bsum[128];

// ---------------------------------------------------------------------------
// scan1: per-1024-chunk exclusive scan of deg -> rowptr + dis/dish tables
// ---------------------------------------------------------------------------
__global__ void scan1_kernel(const int* __restrict__ deg, int* __restrict__ rowptr,
                             float* __restrict__ dis, __half* __restrict__ dish,
                             int* __restrict__ bsum, int n) {
    __shared__ int sh[256];
    int t = threadIdx.x;
    int base = blockIdx.x * 1024 + t * 4;
    int v[4]; int s = 0;
    #pragma unroll
    for (int j = 0; j < 4; j++) {
        v[j] = (base + j < n) ? deg[base + j] : 0;
        if (base + j < n) {
            float r = rsqrtf((float)(v[j] + 1));
            dis[base + j] = r;
            dish[base + j] = __float2half_rn(r);
        }
        s += v[j];
    }
    sh[t] = s;
    for (int off = 1; off < 256; off <<= 1) {
        __syncthreads();
        int x = (t >= off) ? sh[t - off] : 0;
        __syncthreads();
        sh[t] += x;
    }
    __syncthreads();
    int excl = sh[t] - s;
    int run = 0;
    #pragma unroll
    for (int j = 0; j < 4; j++) {
        if (base + j < n) rowptr[base + j] = excl + run;
        run += v[j];
    }
    if (t == 255) bsum[blockIdx.x] = sh[255];
}

__global__ void scan2_kernel(int* __restrict__ bsum, int nb) {
    __shared__ int sh[128];
    int t = threadIdx.x;
    int v = (t < nb) ? bsum[t] : 0;
    sh[t] = v;
    for (int off = 1; off < 128; off <<= 1) {
        __syncthreads();
        int x = (t >= off) ? sh[t - off] : 0;
        __syncthreads();
        sh[t] += x;
    }
    __syncthreads();
    if (t < nb) bsum[t] = sh[t] - v;
}

__global__ void scan3_kernel(const int* __restrict__ bsum, int* __restrict__ rowptr,
                             int* __restrict__ cursor, int n) {
    int i = blockIdx.x * blockDim.x + threadIdx.x;
    if (i < n) {
        int r = rowptr[i] + bsum[i >> 10];
        rowptr[i] = r;
        cursor[i] = r;
    }
}

__global__ void scatter_kernel(const int* __restrict__ src, const int* __restrict__ dst,
                               int* __restrict__ cursor, int* __restrict__ colidx, int E) {
    int e = blockIdx.x * blockDim.x + threadIdx.x;
    if (e < E) {
        int p = atomicAdd(&cursor[dst[e]], 1);
        colidx[p] = src[e];
    }
}

// ---------------------------------------------------------------------------
// GEMM NOUT=64, packed fma.rn.f32x2, fp16 output u.
// Heterogeneous grid: trailing blocks do the degree histogram (layer 0 only).
// ---------------------------------------------------------------------------
template<int K, bool RELU_IN, bool SCALE_OUT>
__global__ void gemm64_kernel(const float* __restrict__ X,
                              const float* __restrict__ W,
                              const float* __restrict__ B,
                              const float* __restrict__ dis,
                              __half* __restrict__ u, int n,
                              const int* __restrict__ edge_dst, int E,
                              int* __restrict__ deg, int gemmBlocks) {
    constexpr int KC = 64;
    constexpr int XSTR = KC + 1;
    __shared__ float  Ws[KC * 64];
    __shared__ float2 Xd[32 * XSTR];

    int t = threadIdx.x;

    if ((int)blockIdx.x >= gemmBlocks) {
        int nb = gridDim.x - gemmBlocks;
        int stride = nb * 256;
        for (int e = (blockIdx.x - gemmBlocks) * 256 + t; e < E; e += stride)
            atomicAdd(&deg[__ldg(edge_dst + e)], 1);
        return;
    }

    int row0 = blockIdx.x * 32;
    int tix = t & 15;
    int tiy = t >> 4;

    unsigned long long acc[2][2];
    acc[0][0] = acc[0][1] = acc[1][0] = acc[1][1] = 0ull;

    for (int k0 = 0; k0 < K; k0 += KC) {
        #pragma unroll
        for (int i = t; i < KC * 64 / 4; i += 256)
            ((float4*)Ws)[i] = ((const float4*)(W + k0 * 64))[i];
        #pragma unroll
        for (int i = t; i < 32 * KC / 4; i += 256) {
            int r = i / (KC / 4);
            int c = (i % (KC / 4)) * 4;
            int gr = row0 + r;
            float4 x = {0.f, 0.f, 0.f, 0.f};
            if (gr < n) {
                x = *(const float4*)(X + (size_t)gr * K + k0 + c);
                if (RELU_IN) {
                    float s = dis[gr];
                    x.x = fmaxf(x.x, 0.f) * s; x.y = fmaxf(x.y, 0.f) * s;
                    x.z = fmaxf(x.z, 0.f) * s; x.w = fmaxf(x.w, 0.f) * s;
                }
            }
            float2* p = &Xd[r * XSTR + c];
            p[0] = make_float2(x.x, x.x); p[1] = make_float2(x.y, x.y);
            p[2] = make_float2(x.z, x.z); p[3] = make_float2(x.w, x.w);
        }
        __syncthreads();

        #pragma unroll
        for (int k = 0; k < KC; k++) {
            ulonglong2 w = *reinterpret_cast<const ulonglong2*>(&Ws[k * 64 + tix * 4]);
            unsigned long long x0 = *reinterpret_cast<const unsigned long long*>(&Xd[(tiy * 2 + 0) * XSTR + k]);
            unsigned long long x1 = *reinterpret_cast<const unsigned long long*>(&Xd[(tiy * 2 + 1) * XSTR + k]);
            asm("fma.rn.f32x2 %0, %1, %2, %0;" : "+l"(acc[0][0]) : "l"(x0), "l"(w.x));
            asm("fma.rn.f32x2 %0, %1, %2, %0;" : "+l"(acc[0][1]) : "l"(x0), "l"(w.y));
            asm("fma.rn.f32x2 %0, %1, %2, %0;" : "+l"(acc[1][0]) : "l"(x1), "l"(w.x));
            asm("fma.rn.f32x2 %0, %1, %2, %0;" : "+l"(acc[1][1]) : "l"(x1), "l"(w.y));
        }
        __syncthreads();
    }

    float4 b4 = *(const float4*)(B + tix * 4);
    #pragma unroll
    for (int r = 0; r < 2; r++) {
        int gr = row0 + tiy * 2 + r;
        if (gr >= n) continue;
        float s = SCALE_OUT ? dis[gr] : 1.f;
        float o0 = (__uint_as_float((unsigned)(acc[r][0] & 0xffffffffu)) + b4.x) * s;
        float o1 = (__uint_as_float((unsigned)(acc[r][0] >> 32))         + b4.y) * s;
        float o2 = (__uint_as_float((unsigned)(acc[r][1] & 0xffffffffu)) + b4.z) * s;
        float o3 = (__uint_as_float((unsigned)(acc[r][1] >> 32))         + b4.w) * s;
        __half2 h01 = __floats2half2_rn(o0, o1);
        __half2 h23 = __floats2half2_rn(o2, o3);
        uint2 pk = make_uint2(*(unsigned*)&h01, *(unsigned*)&h23);
        *(uint2*)(u + (size_t)gr * 64 + tix * 4) = pk;
    }
}

// ---------------------------------------------------------------------------
// Output head GEMM (NOUT=40), fp32 in/out
// ---------------------------------------------------------------------------
template<int K, int NOUT>
__global__ void gemm_head_kernel(const float* __restrict__ X,
                                 const float* __restrict__ W,
                                 const float* __restrict__ B,
                                 const float* __restrict__ dis,
                                 float* __restrict__ out, int n) {
    __shared__ float Ws[K * NOUT];
    __shared__ float Xs[32 * K];

    int t = threadIdx.x;
    int row0 = blockIdx.x * 32;

    #pragma unroll 4
    for (int i = t; i < K * NOUT; i += 256) Ws[i] = W[i];
    #pragma unroll 4
    for (int i = t; i < 32 * K; i += 256) {
        int r = i / K, k = i - r * K;
        int gr = row0 + r;
        float v = 0.f;
        if (gr < n) v = fmaxf(X[(size_t)gr * K + k], 0.f) * dis[gr];
        Xs[i] = v;
    }
    __syncthreads();

    int warp = t >> 5, lane = t & 31;
    int r0 = warp * 4;
    float acc0[4] = {0.f, 0.f, 0.f, 0.f};
    float acc1[4] = {0.f, 0.f, 0.f, 0.f};

    #pragma unroll
    for (int k = 0; k < K; k++) {
        float w0 = Ws[k * NOUT + lane];
        float w1 = (lane + 32 < NOUT) ? Ws[k * NOUT + lane + 32] : 0.f;
        #pragma unroll
        for (int r = 0; r < 4; r++) {
            float xv = Xs[(r0 + r) * K + k];
            acc0[r] = fmaf(xv, w0, acc0[r]);
            acc1[r] = fmaf(xv, w1, acc1[r]);
        }
    }

    float b0 = B[lane];
    float b1 = (lane + 32 < NOUT) ? B[lane + 32] : 0.f;
    #pragma unroll
    for (int r = 0; r < 4; r++) {
        int gr = row0 + r0 + r;
        if (gr >= n) continue;
        out[(size_t)gr * NOUT + lane] = acc0[r] + b0;
        if (lane + 32 < NOUT) out[(size_t)gr * NOUT + lane + 32] = acc1[r] + b1;
    }
}

// ---------------------------------------------------------------------------
// Pull aggregation, fp16 HADD2/HFMA2 accumulation (issue-bound fix).
// 8 lanes per node; lane h covers halfs [h*8, h*8+8) = uint4 = 4 half2.
// Neighbor partial sums in half2 (two sets, chain ~deg/2), combined + self in fp32.
// WEIGHTED=true (layer 0): acc[v] = dis[v]*u[v] + sum dis[s]*u[s]
// ---------------------------------------------------------------------------
template<bool WEIGHTED>
__global__ void pull_kernel(const int* __restrict__ rowptr,
                            const int* __restrict__ deg,
                            const int* __restrict__ colidx,
                            const float* __restrict__ dis,
                            const __half* __restrict__ dish,
                            const __half* __restrict__ u,
                            float* __restrict__ acc, int n) {
    int idx = blockIdx.x * blockDim.x + threadIdx.x;
    int v = idx >> 3;
    if (v >= n) return;
    int h = idx & 7;

    const uint4* uv = (const uint4*)u;   // row stride = 8 uint4

    const __half2 z = __float2half2_rn(0.f);
    __half2 s0[4] = {z, z, z, z};
    __half2 s1[4] = {z, z, z, z};

    int p0 = __ldg(rowptr + v);
    int d  = __ldg(deg + v);

    int j = 0;
    for (; j + 2 <= d; j += 2) {
        int c0 = __ldg(colidx + p0 + j);
        int c1 = __ldg(colidx + p0 + j + 1);
        uint4 x0 = __ldg(uv + (size_t)c0 * 8 + h);
        uint4 x1 = __ldg(uv + (size_t)c1 * 8 + h);
        if (WEIGHTED) {
            __half2 w0 = __half2half2(__ldg(dish + c0));
            __half2 w1 = __half2half2(__ldg(dish + c1));
            s0[0] = __hfma2(w0, *(__half2*)&x0.x, s0[0]);
            s0[1] = __hfma2(w0, *(__half2*)&x0.y, s0[1]);
            s0[2] = __hfma2(w0, *(__half2*)&x0.z, s0[2]);
            s0[3] = __hfma2(w0, *(__half2*)&x0.w, s0[3]);
            s1[0] = __hfma2(w1, *(__half2*)&x1.x, s1[0]);
            s1[1] = __hfma2(w1, *(__half2*)&x1.y, s1[1]);
            s1[2] = __hfma2(w1, *(__half2*)&x1.z, s1[2]);
            s1[3] = __hfma2(w1, *(__half2*)&x1.w, s1[3]);
        } else {
            s0[0] = __hadd2(s0[0], *(__half2*)&x0.x);
            s0[1] = __hadd2(s0[1], *(__half2*)&x0.y);
            s0[2] = __hadd2(s0[2], *(__half2*)&x0.z);
            s0[3] = __hadd2(s0[3], *(__half2*)&x0.w);
            s1[0] = __hadd2(s1[0], *(__half2*)&x1.x);
            s1[1] = __hadd2(s1[1], *(__half2*)&x1.y);
            s1[2] = __hadd2(s1[2], *(__half2*)&x1.z);
            s1[3] = __hadd2(s1[3], *(__half2*)&x1.w);
        }
    }
    if (j < d) {
        int c0 = __ldg(colidx + p0 + j);
        uint4 x0 = __ldg(uv + (size_t)c0 * 8 + h);
        if (WEIGHTED) {
            __half2 w0 = __half2half2(__ldg(dish + c0));
            s0[0] = __hfma2(w0, *(__half2*)&x0.x, s0[0]);
            s0[1] = __hfma2(w0, *(__half2*)&x0.y, s0[1]);
            s0[2] = __hfma2(w0, *(__half2*)&x0.z, s0[2]);
            s0[3] = __hfma2(w0, *(__half2*)&x0.w, s0[3]);
        } else {
            s0[0] = __hadd2(s0[0], *(__half2*)&x0.x);
            s0[1] = __hadd2(s0[1], *(__half2*)&x0.y);
            s0[2] = __hadd2(s0[2], *(__half2*)&x0.z);
            s0[3] = __hadd2(s0[3], *(__half2*)&x0.w);
        }
    }

    // Combine partials + self term in fp32
    uint4 ps = __ldg(uv + (size_t)v * 8 + h);
    float sv = WEIGHTED ? __ldg(dis + v) : 1.f;

    float out[8];
    #pragma unroll
    for (int k = 0; k < 4; k++) {
        float2 f0 = __half22float2(s0[k]);
        float2 f1 = __half22float2(s1[k]);
        float2 fs = __half22float2(*((__half2*)&ps.x + k));
        out[k * 2 + 0] = f0.x + f1.x + fs.x * sv;
        out[k * 2 + 1] = f0.y + f1.y + fs.y * sv;
    }
    float4* ap = (float4*)(acc + (size_t)v * 64 + h * 8);
    ap[0] = make_float4(out[0], out[1], out[2], out[3]);
    ap[1] = make_float4(out[4], out[5], out[6], out[7]);
}

// ---------------------------------------------------------------------------
extern "C" void kernel_launch(void* const* d_in, const int* in_sizes, int n_in,
                              void* d_out, int out_size) {
    const float* x    = (const float*)d_in[0];
    const int*   ei   = (const int*)d_in[1];
    const float* W0   = (const float*)d_in[2];
    const float* b0   = (const float*)d_in[3];
    const float* W1   = (const float*)d_in[4];
    const float* b1   = (const float*)d_in[5];
    const float* W2   = (const float*)d_in[6];
    const float* b2   = (const float*)d_in[7];
    const float* Wout = (const float*)d_in[8];
    const float* bout = (const float*)d_in[9];
    float* out = (float*)d_out;

    const int N = in_sizes[0] / F_IN;
    const int E = in_sizes[1] / 2;
    const int* src = ei;
    const int* dst = ei + E;

    __half *uA, *uB, *dish;
    float *accA, *accB, *dis;
    int *deg, *rowptr, *cursor, *colidx, *bsum;
    cudaGetSymbolAddress((void**)&uA,     g_uA);
    cudaGetSymbolAddress((void**)&uB,     g_uB);
    cudaGetSymbolAddress((void**)&accA,   g_accA);
    cudaGetSymbolAddress((void**)&accB,   g_accB);
    cudaGetSymbolAddress((void**)&deg,    g_deg);
    cudaGetSymbolAddress((void**)&dis,    g_dis);
    cudaGetSymbolAddress((void**)&dish,   g_dish);
    cudaGetSymbolAddress((void**)&rowptr, g_rowptr);
    cudaGetSymbolAddress((void**)&cursor, g_cursor);
    cudaGetSymbolAddress((void**)&colidx, g_colidx);
    cudaGetSymbolAddress((void**)&bsum,   g_bsum);

    const int TPB = 256;
    int gemmBlocks = (N + 31) / 32;
    int countBlocks = 2048;
    dim3 fused_grid(gemmBlocks + countBlocks);
    dim3 g64_grid(gemmBlocks);
    dim3 pull_grid(((size_t)N * 8 + TPB - 1) / TPB);
    int nscan = (N + 1023) / 1024;

    // Layer-0 GEMM (no dis dependency; unscaled output) fused with degree count
    cudaMemsetAsync(deg, 0, N * sizeof(int), 0);
    gemm64_kernel<F_IN, false, false><<<fused_grid, TPB>>>(
        x, W0, b0, dis, uA, N, dst, E, deg, gemmBlocks);

    // CSR build (dst-grouped) + dis tables
    scan1_kernel<<<nscan, 256>>>(deg, rowptr, dis, dish, bsum, N);
    scan2_kernel<<<1, 128>>>(bsum, nscan);
    scan3_kernel<<<(N + TPB - 1) / TPB, TPB>>>(bsum, rowptr, cursor, N);
    scatter_kernel<<<(E + TPB - 1) / TPB, TPB>>>(src, dst, cursor, colidx, E);

    // Layer 0 aggregation (weighted: applies dis[src] and dis[v] here)
    pull_kernel<true><<<pull_grid, TPB>>>(rowptr, deg, colidx, dis, dish, uA, accA, N);
    // Layer 1
    gemm64_kernel<HID, true, true><<<g64_grid, TPB>>>(accA, W1, b1, dis, uB, N, nullptr, 0, nullptr, gemmBlocks);
    pull_kernel<false><<<pull_grid, TPB>>>(rowptr, deg, colidx, dis, dish, uB, accB, N);
    // Layer 2
    gemm64_kernel<HID, true, true><<<g64_grid, TPB>>>(accB, W2, b2, dis, uA, N, nullptr, 0, nullptr, gemmBlocks);
    pull_kernel<false><<<pull_grid, TPB>>>(rowptr, deg, colidx, dis, dish, uA, accA, N);
    // Head
    gemm_head_kernel<HID, OUTD><<<g64_grid, TPB>>>(accA, Wout, bout, dis, out, N);
}

// round 6
// speedup vs baseline: 1.1974x; 1.0541x over previous
#include <cuda_runtime.h>
#include <cuda_fp16.h>
#include <cstdint>

#define NN   100000
#define EE   1600000
#define F_IN 128
#define HID  64
#define OUTD 40

// Scratch (device globals — allocation is forbidden)
__device__ __half g_uA[NN * HID];     // fp16 messages
__device__ __half g_uB[NN * HID];
__device__ int    g_deg[NN];
__device__ float  g_dis[NN];
__device__ __half g_dish[NN];
__device__ int    g_rowptr[NN];
__device__ int    g_cursor[NN];
__device__ int    g_colidx[EE];
__device__ int    g_bsum[128];

// ---------------------------------------------------------------------------
// scan1: per-1024-chunk exclusive scan of deg -> rowptr + dis/dish tables
// ---------------------------------------------------------------------------
__global__ void scan1_kernel(const int* __restrict__ deg, int* __restrict__ rowptr,
                             float* __restrict__ dis, __half* __restrict__ dish,
                             int* __restrict__ bsum, int n) {
    __shared__ int sh[256];
    int t = threadIdx.x;
    int base = blockIdx.x * 1024 + t * 4;
    int v[4]; int s = 0;
    #pragma unroll
    for (int j = 0; j < 4; j++) {
        v[j] = (base + j < n) ? deg[base + j] : 0;
        if (base + j < n) {
            float r = rsqrtf((float)(v[j] + 1));
            dis[base + j] = r;
            dish[base + j] = __float2half_rn(r);
        }
        s += v[j];
    }
    sh[t] = s;
    for (int off = 1; off < 256; off <<= 1) {
        __syncthreads();
        int x = (t >= off) ? sh[t - off] : 0;
        __syncthreads();
        sh[t] += x;
    }
    __syncthreads();
    int excl = sh[t] - s;
    int run = 0;
    #pragma unroll
    for (int j = 0; j < 4; j++) {
        if (base + j < n) rowptr[base + j] = excl + run;
        run += v[j];
    }
    if (t == 255) bsum[blockIdx.x] = sh[255];
}

__global__ void scan2_kernel(int* __restrict__ bsum, int nb) {
    __shared__ int sh[128];
    int t = threadIdx.x;
    int v = (t < nb) ? bsum[t] : 0;
    sh[t] = v;
    for (int off = 1; off < 128; off <<= 1) {
        __syncthreads();
        int x = (t >= off) ? sh[t - off] : 0;
        __syncthreads();
        sh[t] += x;
    }
    __syncthreads();
    if (t < nb) bsum[t] = sh[t] - v;
}

__global__ void scan3_kernel(const int* __restrict__ bsum, int* __restrict__ rowptr,
                             int* __restrict__ cursor, int n) {
    int i = blockIdx.x * blockDim.x + threadIdx.x;
    if (i < n) {
        int r = rowptr[i] + bsum[i >> 10];
        rowptr[i] = r;
        cursor[i] = r;
    }
}

__global__ void scatter_kernel(const int* __restrict__ src, const int* __restrict__ dst,
                               int* __restrict__ cursor, int* __restrict__ colidx, int E) {
    int e = blockIdx.x * blockDim.x + threadIdx.x;
    if (e < E) {
        int p = atomicAdd(&cursor[dst[e]], 1);
        colidx[p] = src[e];
    }
}

// ---------------------------------------------------------------------------
// Layer-0 GEMM: X fp32 [n,128] @ W [128,64] + b -> u fp16 (unscaled).
// Heterogeneous grid: trailing blocks do the degree histogram.
// ---------------------------------------------------------------------------
__global__ void gemm0_kernel(const float* __restrict__ X,
                             const float* __restrict__ W,
                             const float* __restrict__ B,
                             __half* __restrict__ u, int n,
                             const int* __restrict__ edge_dst, int E,
                             int* __restrict__ deg, int gemmBlocks) {
    constexpr int K = F_IN;
    constexpr int KC = 64;
    constexpr int XSTR = KC + 1;
    __shared__ float  Ws[KC * 64];
    __shared__ float2 Xd[32 * XSTR];

    int t = threadIdx.x;

    if ((int)blockIdx.x >= gemmBlocks) {
        int nb = gridDim.x - gemmBlocks;
        int stride = nb * 256;
        for (int e = (blockIdx.x - gemmBlocks) * 256 + t; e < E; e += stride)
            atomicAdd(&deg[__ldg(edge_dst + e)], 1);
        return;
    }

    int row0 = blockIdx.x * 32;
    int tix = t & 15;
    int tiy = t >> 4;

    unsigned long long acc[2][2];
    acc[0][0] = acc[0][1] = acc[1][0] = acc[1][1] = 0ull;

    for (int k0 = 0; k0 < K; k0 += KC) {
        #pragma unroll
        for (int i = t; i < KC * 64 / 4; i += 256)
            ((float4*)Ws)[i] = ((const float4*)(W + k0 * 64))[i];
        #pragma unroll
        for (int i = t; i < 32 * KC / 4; i += 256) {
            int r = i / (KC / 4);
            int c = (i % (KC / 4)) * 4;
            int gr = row0 + r;
            float4 x = {0.f, 0.f, 0.f, 0.f};
            if (gr < n) x = *(const float4*)(X + (size_t)gr * K + k0 + c);
            float2* p = &Xd[r * XSTR + c];
            p[0] = make_float2(x.x, x.x); p[1] = make_float2(x.y, x.y);
            p[2] = make_float2(x.z, x.z); p[3] = make_float2(x.w, x.w);
        }
        __syncthreads();

        #pragma unroll
        for (int k = 0; k < KC; k++) {
            ulonglong2 w = *reinterpret_cast<const ulonglong2*>(&Ws[k * 64 + tix * 4]);
            unsigned long long x0 = *reinterpret_cast<const unsigned long long*>(&Xd[(tiy * 2 + 0) * XSTR + k]);
            unsigned long long x1 = *reinterpret_cast<const unsigned long long*>(&Xd[(tiy * 2 + 1) * XSTR + k]);
            asm("fma.rn.f32x2 %0, %1, %2, %0;" : "+l"(acc[0][0]) : "l"(x0), "l"(w.x));
            asm("fma.rn.f32x2 %0, %1, %2, %0;" : "+l"(acc[0][1]) : "l"(x0), "l"(w.y));
            asm("fma.rn.f32x2 %0, %1, %2, %0;" : "+l"(acc[1][0]) : "l"(x1), "l"(w.x));
            asm("fma.rn.f32x2 %0, %1, %2, %0;" : "+l"(acc[1][1]) : "l"(x1), "l"(w.y));
        }
        __syncthreads();
    }

    float4 b4 = *(const float4*)(B + tix * 4);
    #pragma unroll
    for (int r = 0; r < 2; r++) {
        int gr = row0 + tiy * 2 + r;
        if (gr >= n) continue;
        float o0 = __uint_as_float((unsigned)(acc[r][0] & 0xffffffffu)) + b4.x;
        float o1 = __uint_as_float((unsigned)(acc[r][0] >> 32))         + b4.y;
        float o2 = __uint_as_float((unsigned)(acc[r][1] & 0xffffffffu)) + b4.z;
        float o3 = __uint_as_float((unsigned)(acc[r][1] >> 32))         + b4.w;
        __half2 h01 = __floats2half2_rn(o0, o1);
        __half2 h23 = __floats2half2_rn(o2, o3);
        uint2 pk = make_uint2(*(unsigned*)&h01, *(unsigned*)&h23);
        *(uint2*)(u + (size_t)gr * 64 + tix * 4) = pk;
    }
}

// ---------------------------------------------------------------------------
// Phase-1 helper: aggregate node v (8 lanes, lane h) from fp16 u, return
// relu(acc)*dis[v] for this lane's 8 columns. fp16 partials, fp32 combine.
// ---------------------------------------------------------------------------
template<bool WEIGHTED>
__device__ __forceinline__ void aggregate_node(
    int v, int h,
    const int* __restrict__ rowptr, const int* __restrict__ deg,
    const int* __restrict__ colidx, const float* __restrict__ dis,
    const __half* __restrict__ dish, const __half* __restrict__ u,
    float out[8])
{
    const uint4* uv = (const uint4*)u;   // row stride = 8 uint4
    const __half2 z = __float2half2_rn(0.f);
    __half2 s0[4] = {z, z, z, z};
    __half2 s1[4] = {z, z, z, z};

    int p0 = __ldg(rowptr + v);
    int d  = __ldg(deg + v);

    int j = 0;
    for (; j + 2 <= d; j += 2) {
        int c0 = __ldg(colidx + p0 + j);
        int c1 = __ldg(colidx + p0 + j + 1);
        uint4 x0 = __ldg(uv + (size_t)c0 * 8 + h);
        uint4 x1 = __ldg(uv + (size_t)c1 * 8 + h);
        if (WEIGHTED) {
            __half2 w0 = __half2half2(__ldg(dish + c0));
            __half2 w1 = __half2half2(__ldg(dish + c1));
            s0[0] = __hfma2(w0, *(__half2*)&x0.x, s0[0]);
            s0[1] = __hfma2(w0, *(__half2*)&x0.y, s0[1]);
            s0[2] = __hfma2(w0, *(__half2*)&x0.z, s0[2]);
            s0[3] = __hfma2(w0, *(__half2*)&x0.w, s0[3]);
            s1[0] = __hfma2(w1, *(__half2*)&x1.x, s1[0]);
            s1[1] = __hfma2(w1, *(__half2*)&x1.y, s1[1]);
            s1[2] = __hfma2(w1, *(__half2*)&x1.z, s1[2]);
            s1[3] = __hfma2(w1, *(__half2*)&x1.w, s1[3]);
        } else {
            s0[0] = __hadd2(s0[0], *(__half2*)&x0.x);
            s0[1] = __hadd2(s0[1], *(__half2*)&x0.y);
            s0[2] = __hadd2(s0[2], *(__half2*)&x0.z);
            s0[3] = __hadd2(s0[3], *(__half2*)&x0.w);
            s1[0] = __hadd2(s1[0], *(__half2*)&x1.x);
            s1[1] = __hadd2(s1[1], *(__half2*)&x1.y);
            s1[2] = __hadd2(s1[2], *(__half2*)&x1.z);
            s1[3] = __hadd2(s1[3], *(__half2*)&x1.w);
        }
    }
    if (j < d) {
        int c0 = __ldg(colidx + p0 + j);
        uint4 x0 = __ldg(uv + (size_t)c0 * 8 + h);
        if (WEIGHTED) {
            __half2 w0 = __half2half2(__ldg(dish + c0));
            s0[0] = __hfma2(w0, *(__half2*)&x0.x, s0[0]);
            s0[1] = __hfma2(w0, *(__half2*)&x0.y, s0[1]);
            s0[2] = __hfma2(w0, *(__half2*)&x0.z, s0[2]);
            s0[3] = __hfma2(w0, *(__half2*)&x0.w, s0[3]);
        } else {
            s0[0] = __hadd2(s0[0], *(__half2*)&x0.x);
            s0[1] = __hadd2(s0[1], *(__half2*)&x0.y);
            s0[2] = __hadd2(s0[2], *(__half2*)&x0.z);
            s0[3] = __hadd2(s0[3], *(__half2*)&x0.w);
        }
    }

    uint4 ps = __ldg(uv + (size_t)v * 8 + h);
    float dv = __ldg(dis + v);
    float sv = WEIGHTED ? dv : 1.f;

    #pragma unroll
    for (int k = 0; k < 4; k++) {
        float2 f0 = __half22float2(s0[k]);
        float2 f1 = __half22float2(s1[k]);
        float2 fs = __half22float2(*((__half2*)&ps.x + k));
        float a0 = f0.x + f1.x + fs.x * sv;
        float a1 = f0.y + f1.y + fs.y * sv;
        out[k * 2 + 0] = fmaxf(a0, 0.f) * dv;   // next-layer input: relu * dis[v]
        out[k * 2 + 1] = fmaxf(a1, 0.f) * dv;
    }
}

// ---------------------------------------------------------------------------
// Fused pull + GEMM64: u_out = half( dis_or_1 ... ) — output UNSCALED+raw for
// next pull: u_out = fp16( agg_input @ W + b ) scaled by dis[row].
// Block 256 thr: phase1 = 32 nodes aggregated (t>>3 node, t&7 lane);
// phase2 = 32x64 GEMM (f32x2).
// ---------------------------------------------------------------------------
template<bool WEIGHTED>
__global__ void fused64_kernel(const int* __restrict__ rowptr,
                               const int* __restrict__ deg,
                               const int* __restrict__ colidx,
                               const float* __restrict__ dis,
                               const __half* __restrict__ dish,
                               const __half* __restrict__ u_in,
                               const float* __restrict__ W,
                               const float* __restrict__ B,
                               __half* __restrict__ u_out, int n) {
    constexpr int KC = 64;
    constexpr int XSTR = KC + 1;
    __shared__ float  Ws[KC * 64];
    __shared__ float2 Xd[32 * XSTR];

    int t = threadIdx.x;
    int row0 = blockIdx.x * 32;

    // Weight tile load (independent of phase 1)
    #pragma unroll
    for (int i = t; i < KC * 64 / 4; i += 256)
        ((float4*)Ws)[i] = ((const float4*)W)[i];

    // Phase 1: aggregate 32 nodes -> Xd (duplicated f32x2)
    {
        int r = t >> 3;           // local node 0..31
        int h = t & 7;            // lane covers cols [h*8, h*8+8)
        int v = row0 + r;
        float xv[8] = {0,0,0,0,0,0,0,0};
        if (v < n)
            aggregate_node<WEIGHTED>(v, h, rowptr, deg, colidx, dis, dish, u_in, xv);
        float2* p = &Xd[r * XSTR + h * 8];
        #pragma unroll
        for (int k = 0; k < 8; k++) p[k] = make_float2(xv[k], xv[k]);
    }
    __syncthreads();

    // Phase 2: 32x64 GEMM
    int tix = t & 15;
    int tiy = t >> 4;
    unsigned long long acc[2][2];
    acc[0][0] = acc[0][1] = acc[1][0] = acc[1][1] = 0ull;

    #pragma unroll
    for (int k = 0; k < KC; k++) {
        ulonglong2 w = *reinterpret_cast<const ulonglong2*>(&Ws[k * 64 + tix * 4]);
        unsigned long long x0 = *reinterpret_cast<const unsigned long long*>(&Xd[(tiy * 2 + 0) * XSTR + k]);
        unsigned long long x1 = *reinterpret_cast<const unsigned long long*>(&Xd[(tiy * 2 + 1) * XSTR + k]);
        asm("fma.rn.f32x2 %0, %1, %2, %0;" : "+l"(acc[0][0]) : "l"(x0), "l"(w.x));
        asm("fma.rn.f32x2 %0, %1, %2, %0;" : "+l"(acc[0][1]) : "l"(x0), "l"(w.y));
        asm("fma.rn.f32x2 %0, %1, %2, %0;" : "+l"(acc[1][0]) : "l"(x1), "l"(w.x));
        asm("fma.rn.f32x2 %0, %1, %2, %0;" : "+l"(acc[1][1]) : "l"(x1), "l"(w.y));
    }

    float4 b4 = *(const float4*)(B + tix * 4);
    #pragma unroll
    for (int r = 0; r < 2; r++) {
        int gr = row0 + tiy * 2 + r;
        if (gr >= n) continue;
        float s = __ldg(dis + gr);
        float o0 = (__uint_as_float((unsigned)(acc[r][0] & 0xffffffffu)) + b4.x) * s;
        float o1 = (__uint_as_float((unsigned)(acc[r][0] >> 32))         + b4.y) * s;
        float o2 = (__uint_as_float((unsigned)(acc[r][1] & 0xffffffffu)) + b4.z) * s;
        float o3 = (__uint_as_float((unsigned)(acc[r][1] >> 32))         + b4.w) * s;
        __half2 h01 = __floats2half2_rn(o0, o1);
        __half2 h23 = __floats2half2_rn(o2, o3);
        uint2 pk = make_uint2(*(unsigned*)&h01, *(unsigned*)&h23);
        *(uint2*)(u_out + (size_t)gr * 64 + tix * 4) = pk;
    }
}

// ---------------------------------------------------------------------------
// Fused pull + head GEMM (K=64, NOUT=40), fp32 output.
// ---------------------------------------------------------------------------
__global__ void fused_head_kernel(const int* __restrict__ rowptr,
                                  const int* __restrict__ deg,
                                  const int* __restrict__ colidx,
                                  const float* __restrict__ dis,
                                  const __half* __restrict__ dish,
                                  const __half* __restrict__ u_in,
                                  const float* __restrict__ W,
                                  const float* __restrict__ B,
                                  float* __restrict__ out, int n) {
    constexpr int K = HID, NOUT = OUTD;
    __shared__ float Ws[K * NOUT];
    __shared__ float Xs[32 * K];

    int t = threadIdx.x;
    int row0 = blockIdx.x * 32;

    #pragma unroll 4
    for (int i = t; i < K * NOUT; i += 256) Ws[i] = W[i];

    // Phase 1: aggregate 32 nodes -> Xs
    {
        int r = t >> 3;
        int h = t & 7;
        int v = row0 + r;
        float xv[8] = {0,0,0,0,0,0,0,0};
        if (v < n)
            aggregate_node<false>(v, h, rowptr, deg, colidx, dis, dish, u_in, xv);
        float* p = &Xs[r * K + h * 8];
        #pragma unroll
        for (int k = 0; k < 8; k++) p[k] = xv[k];
    }
    __syncthreads();

    // Phase 2: head GEMM
    int warp = t >> 5, lane = t & 31;
    int r0 = warp * 4;
    float acc0[4] = {0.f, 0.f, 0.f, 0.f};
    float acc1[4] = {0.f, 0.f, 0.f, 0.f};

    #pragma unroll
    for (int k = 0; k < K; k++) {
        float w0 = Ws[k * NOUT + lane];
        float w1 = (lane + 32 < NOUT) ? Ws[k * NOUT + lane + 32] : 0.f;
        #pragma unroll
        for (int r = 0; r < 4; r++) {
            float xv = Xs[(r0 + r) * K + k];
            acc0[r] = fmaf(xv, w0, acc0[r]);
            acc1[r] = fmaf(xv, w1, acc1[r]);
        }
    }

    float b0 = B[lane];
    float b1 = (lane + 32 < NOUT) ? B[lane + 32] : 0.f;
    #pragma unroll
    for (int r = 0; r < 4; r++) {
        int gr = row0 + r0 + r;
        if (gr >= n) continue;
        out[(size_t)gr * NOUT + lane] = acc0[r] + b0;
        if (lane + 32 < NOUT) out[(size_t)gr * NOUT + lane + 32] = acc1[r] + b1;
    }
}

// ---------------------------------------------------------------------------
extern "C" void kernel_launch(void* const* d_in, const int* in_sizes, int n_in,
                              void* d_out, int out_size) {
    const float* x    = (const float*)d_in[0];
    const int*   ei   = (const int*)d_in[1];
    const float* W0   = (const float*)d_in[2];
    const float* b0   = (const float*)d_in[3];
    const float* W1   = (const float*)d_in[4];
    const float* b1   = (const float*)d_in[5];
    const float* W2   = (const float*)d_in[6];
    const float* b2   = (const float*)d_in[7];
    const float* Wout = (const float*)d_in[8];
    const float* bout = (const float*)d_in[9];
    float* out = (float*)d_out;

    const int N = in_sizes[0] / F_IN;
    const int E = in_sizes[1] / 2;
    const int* src = ei;
    const int* dst = ei + E;

    __half *uA, *uB, *dish;
    float *dis;
    int *deg, *rowptr, *cursor, *colidx, *bsum;
    cudaGetSymbolAddress((void**)&uA,     g_uA);
    cudaGetSymbolAddress((void**)&uB,     g_uB);
    cudaGetSymbolAddress((void**)&deg,    g_deg);
    cudaGetSymbolAddress((void**)&dis,    g_dis);
    cudaGetSymbolAddress((void**)&dish,   g_dish);
    cudaGetSymbolAddress((void**)&rowptr, g_rowptr);
    cudaGetSymbolAddress((void**)&cursor, g_cursor);
    cudaGetSymbolAddress((void**)&colidx, g_colidx);
    cudaGetSymbolAddress((void**)&bsum,   g_bsum);

    const int TPB = 256;
    int gemmBlocks = (N + 31) / 32;
    int countBlocks = 2048;
    dim3 fused0_grid(gemmBlocks + countBlocks);
    dim3 layer_grid(gemmBlocks);
    int nscan = (N + 1023) / 1024;

    // Layer-0 GEMM (no dis dependency) fused with degree count
    cudaMemsetAsync(deg, 0, N * sizeof(int), 0);
    gemm0_kernel<<<fused0_grid, TPB>>>(x, W0, b0, uA, N, dst, E, deg, gemmBlocks);

    // CSR build (dst-grouped) + dis tables
    scan1_kernel<<<nscan, 256>>>(deg, rowptr, dis, dish, bsum, N);
    scan2_kernel<<<1, 128>>>(bsum, nscan);
    scan3_kernel<<<(N + TPB - 1) / TPB, TPB>>>(bsum, rowptr, cursor, N);
    scatter_kernel<<<(E + TPB - 1) / TPB, TPB>>>(src, dst, cursor, colidx, E);

    // Layer 1 = pull0 (weighted) + GEMM(W1)
    fused64_kernel<true><<<layer_grid, TPB>>>(rowptr, deg, colidx, dis, dish, uA, W1, b1, uB, N);
    // Layer 2 = pull1 + GEMM(W2)
    fused64_kernel<false><<<layer_grid, TPB>>>(rowptr, deg, colidx, dis, dish, uB, W2, b2, uA, N);
    // Head = pull2 + GEMM(Wout)
    fused_head_kernel<<<layer_grid, TPB>>>(rowptr, deg, colidx, dis, dish, uA, Wout, bout, out, N);
}